// round 10
// baseline (speedup 1.0000x reference)
#include <cuda_runtime.h>
#include <math.h>

#define HID   1024
#define BSZ   16
#define NOPT  4
#define ROWS  (BSZ*NOPT)    // 64
#define TRUN  2
#define SEQ   1536
#define PLEN  512
#define QLEN  128

#define NTILE  128            // columns per CTA
#define KCHUNK 16             // k per CTA
#define KSPLIT (HID/KCHUNK)   // 64
#define GTHR   128            // threads per gemm CTA

// Scratch (device globals — no allocation allowed)
__device__ float g_feats[ROWS*HID];
__device__ float g_h1[ROWS*HID];
__device__ float g_h2[ROWS*HID];

// ---------------------------------------------------------------------------
// f32x2 helpers
// ---------------------------------------------------------------------------
__device__ __forceinline__ void fma_f32x2(unsigned long long& acc,
                                          unsigned long long a,
                                          unsigned long long b) {
    asm("fma.rn.f32x2 %0, %1, %2, %0;" : "+l"(acc) : "l"(a), "l"(b));
}
__device__ __forceinline__ float lo_f(unsigned long long v) {
    return __uint_as_float((unsigned)(v & 0xFFFFFFFFull));
}
__device__ __forceinline__ float hi_f(unsigned long long v) {
    return __uint_as_float((unsigned)(v >> 32));
}

__device__ __forceinline__ long long opt_at(const void* p, bool is64, int i) {
    if (is64) return ((const long long*)p)[i];
    return (long long)((const int*)p)[i];
}

// ---------------------------------------------------------------------------
// 1) prep: blocks [0,256) bias-init h1/h2; blocks [256,320) feats rows.
//    Also zeroes the loss output slot (graph-ordered before gemv_loss).
// ---------------------------------------------------------------------------
__global__ void __launch_bounds__(256)
prep_kernel(const float* __restrict__ emb, const void* __restrict__ opt_length,
            const float* __restrict__ b1, const float* __restrict__ b2,
            float* __restrict__ out, int out_size) {
    if (blockIdx.x == 0 && threadIdx.x == 0) {
        if (out_size == 1)             out[0] = 0.f;
        else if (out_size >= ROWS + 1) out[ROWS] = 0.f;
    }

    if (blockIdx.x < 256) {
        int i = blockIdx.x * 256 + threadIdx.x;     // 0..65535
        int j = i & (HID - 1);
        g_h1[i] = b1[j];
        g_h2[i] = b2[j];
        return;
    }
    int row = blockIdx.x - 256;      // b*NOPT + o
    int b = row >> 2, o = row & 3;

    bool is64 = (((const int*)opt_length)[1] == 0);
    long long cs = 0;
    for (int i = 0; i <= o; i++) cs += opt_at(opt_length, is64, i);
    int ohead = PLEN + QLEN + (int)cs;
    int otail = ohead + (int)opt_at(opt_length, is64, o + 1) - 1;
    int pos[6] = {0, PLEN - 1, PLEN, PLEN + QLEN - 1, ohead, otail};

    int h4 = threadIdx.x * 4;
    float4 acc = make_float4(0.f, 0.f, 0.f, 0.f);
    #pragma unroll
    for (int t = 0; t < TRUN; t++) {
        const float* base = emb + (size_t)(t * BSZ + b) * SEQ * HID;
        #pragma unroll
        for (int p = 0; p < 6; p++) {
            float4 v = *(const float4*)(base + (size_t)pos[p] * HID + h4);
            acc.x += v.x; acc.y += v.y; acc.z += v.z; acc.w += v.w;
        }
    }
    const float s = 0.25f;
    *(float4*)(g_feats + (size_t)row * HID + h4) =
        make_float4(acc.x * s, acc.y * s, acc.z * s, acc.w * s);
}

// ---------------------------------------------------------------------------
// 2) Split-K GEMM, W streamed from global (each W element belongs to exactly
//    one CTA), A in smem stored DUPLICATED (a,a) so FFMA2 operands need no
//    packing movs. Tile 64 rows x 128 cols x 16 k; grid (8,64)=512 CTAs,
//    128 threads, 8x8 microtile. Inner loop per k per thread:
//    4x LDS.128 (broadcast) + 2x LDG.128 (w, pre-packed col pairs) + 32 FFMA2.
//    Epilogue red.global.add.v4 onto bias-initialized out.
// ---------------------------------------------------------------------------
template <int LAYER>
__global__ void __launch_bounds__(GTHR)
gemm_kernel(const float* __restrict__ W) {
    __shared__ float2 As2[KCHUNK][66];   // [k][row] duplicated pairs, pad 2

    const float* A  = (LAYER == 0) ? g_feats : g_h1;
    float*      out = (LAYER == 0) ? g_h1    : g_h2;

    const int n0  = blockIdx.x * NTILE;
    const int k0  = blockIdx.y * KCHUNK;
    const int tid = threadIdx.x;

    // Load A tile 64 rows x 16 k (float4 over k), store duplicated-transposed.
    {
        int r  = tid >> 2;              // 0..31
        int k4 = (tid & 3) * 4;         // 0,4,8,12
        #pragma unroll
        for (int rr = 0; rr < 2; rr++) {
            int row = r + rr * 32;
            float4 v = *(const float4*)(A + (size_t)row * HID + k0 + k4);
            if (LAYER == 1) {
                v.x = fmaxf(v.x, 0.f); v.y = fmaxf(v.y, 0.f);
                v.z = fmaxf(v.z, 0.f); v.w = fmaxf(v.w, 0.f);
            }
            As2[k4 + 0][row] = make_float2(v.x, v.x);
            As2[k4 + 1][row] = make_float2(v.y, v.y);
            As2[k4 + 2][row] = make_float2(v.z, v.z);
            As2[k4 + 3][row] = make_float2(v.w, v.w);
        }
    }
    __syncthreads();

    const int r0 = (tid >> 4) * 8;      // 0..56
    const int c0 = (tid & 15) * 8;      // 0..120
    const float* Wp = W + (size_t)k0 * HID + n0 + c0;

    unsigned long long acc[8][4] = {};  // [row][colpair]
    #pragma unroll
    for (int k = 0; k < KCHUNK; k++) {
        // W col pairs come pre-packed from memory.
        ulonglong2 wq0 = *(const ulonglong2*)(Wp + (size_t)k * HID);
        ulonglong2 wq1 = *(const ulonglong2*)(Wp + (size_t)k * HID + 4);
        // A duplicated pairs from smem (broadcast LDS.128, 2 rows each).
        ulonglong2 a01 = *(const ulonglong2*)&As2[k][r0 + 0];
        ulonglong2 a23 = *(const ulonglong2*)&As2[k][r0 + 2];
        ulonglong2 a45 = *(const ulonglong2*)&As2[k][r0 + 4];
        ulonglong2 a67 = *(const ulonglong2*)&As2[k][r0 + 6];

        fma_f32x2(acc[0][0], a01.x, wq0.x); fma_f32x2(acc[0][1], a01.x, wq0.y);
        fma_f32x2(acc[0][2], a01.x, wq1.x); fma_f32x2(acc[0][3], a01.x, wq1.y);
        fma_f32x2(acc[1][0], a01.y, wq0.x); fma_f32x2(acc[1][1], a01.y, wq0.y);
        fma_f32x2(acc[1][2], a01.y, wq1.x); fma_f32x2(acc[1][3], a01.y, wq1.y);
        fma_f32x2(acc[2][0], a23.x, wq0.x); fma_f32x2(acc[2][1], a23.x, wq0.y);
        fma_f32x2(acc[2][2], a23.x, wq1.x); fma_f32x2(acc[2][3], a23.x, wq1.y);
        fma_f32x2(acc[3][0], a23.y, wq0.x); fma_f32x2(acc[3][1], a23.y, wq0.y);
        fma_f32x2(acc[3][2], a23.y, wq1.x); fma_f32x2(acc[3][3], a23.y, wq1.y);
        fma_f32x2(acc[4][0], a45.x, wq0.x); fma_f32x2(acc[4][1], a45.x, wq0.y);
        fma_f32x2(acc[4][2], a45.x, wq1.x); fma_f32x2(acc[4][3], a45.x, wq1.y);
        fma_f32x2(acc[5][0], a45.y, wq0.x); fma_f32x2(acc[5][1], a45.y, wq0.y);
        fma_f32x2(acc[5][2], a45.y, wq1.x); fma_f32x2(acc[5][3], a45.y, wq1.y);
        fma_f32x2(acc[6][0], a67.x, wq0.x); fma_f32x2(acc[6][1], a67.x, wq0.y);
        fma_f32x2(acc[6][2], a67.x, wq1.x); fma_f32x2(acc[6][3], a67.x, wq1.y);
        fma_f32x2(acc[7][0], a67.y, wq0.x); fma_f32x2(acc[7][1], a67.y, wq0.y);
        fma_f32x2(acc[7][2], a67.y, wq1.x); fma_f32x2(acc[7][3], a67.y, wq1.y);
    }

    #pragma unroll
    for (int r = 0; r < 8; r++) {
        float* p = out + (size_t)(r0 + r) * HID + n0 + c0;
        asm volatile("red.global.add.v4.f32 [%0], {%1, %2, %3, %4};"
                     :: "l"(p),
                        "f"(lo_f(acc[r][0])), "f"(hi_f(acc[r][0])),
                        "f"(lo_f(acc[r][1])), "f"(hi_f(acc[r][1])) : "memory");
        asm volatile("red.global.add.v4.f32 [%0], {%1, %2, %3, %4};"
                     :: "l"(p + 4),
                        "f"(lo_f(acc[r][2])), "f"(hi_f(acc[r][2])),
                        "f"(lo_f(acc[r][3])), "f"(hi_f(acc[r][3])) : "memory");
    }
}

// ---------------------------------------------------------------------------
// 3) gemv+loss, batch-per-CTA, NO cross-CTA sync: CTA b computes its 4 logits
//    and red.adds its loss part/16 into the (prep-zeroed) loss slot.
// ---------------------------------------------------------------------------
__global__ void __launch_bounds__(256)
gemv_loss_kernel(const float* __restrict__ W3, const int* __restrict__ y,
                 float* __restrict__ out, int out_size) {
    __shared__ float red[8];
    __shared__ float lsh[NOPT];

    const int b    = blockIdx.x;        // batch 0..15
    const int tid  = threadIdx.x;
    const int o    = tid >> 6;          // option 0..3
    const int lane = tid & 63;

    const float* h = g_h2 + (size_t)(b * NOPT + o) * HID;
    float s = 0.f;
    #pragma unroll
    for (int i = 0; i < 4; i++) {       // 64 lanes * 4 iters * float4 = 1024
        int k = (lane + i * 64) * 4;
        float4 hv = *(const float4*)(h + k);
        float4 wv = *(const float4*)(W3 + k);
        s += fmaxf(hv.x, 0.f) * wv.x + fmaxf(hv.y, 0.f) * wv.y
           + fmaxf(hv.z, 0.f) * wv.z + fmaxf(hv.w, 0.f) * wv.w;
    }
    #pragma unroll
    for (int off = 16; off; off >>= 1)
        s += __shfl_down_sync(0xFFFFFFFFu, s, off);
    if ((tid & 31) == 0) red[tid >> 5] = s;
    __syncthreads();

    if (tid < NOPT) lsh[tid] = red[2 * tid] + red[2 * tid + 1];
    __syncthreads();

    if (tid == 0) {
        float l0 = lsh[0], l1 = lsh[1], l2 = lsh[2], l3 = lsh[3];
        if (out_size >= ROWS) {
            out[b * NOPT + 0] = l0; out[b * NOPT + 1] = l1;
            out[b * NOPT + 2] = l2; out[b * NOPT + 3] = l3;
        }
        float m  = fmaxf(fmaxf(l0, l1), fmaxf(l2, l3));
        float se = expf(l0 - m) + expf(l1 - m) + expf(l2 - m) + expf(l3 - m);
        float lse = m + logf(se);
        int yy = y[b];
        float ly = (yy == 0) ? l0 : (yy == 1) ? l1 : (yy == 2) ? l2 : l3;
        float contrib = -(ly - lse) * (1.0f / (float)BSZ);

        float* dst = (out_size == 1) ? out
                   : (out_size >= ROWS + 1) ? (out + ROWS) : nullptr;
        if (dst)
            asm volatile("red.global.add.f32 [%0], %1;"
                         :: "l"(dst), "f"(contrib) : "memory");
    }
}

// ---------------------------------------------------------------------------
// Launch — 4 kernels
// inputs: 0=embeddings 1=W1 2=b1 3=W2 4=b2 5=W3 6=y 7=opt_length
// ---------------------------------------------------------------------------
extern "C" void kernel_launch(void* const* d_in, const int* in_sizes, int n_in,
                              void* d_out, int out_size) {
    const float* emb = (const float*)d_in[0];
    const float* W1  = (const float*)d_in[1];
    const float* b1  = (const float*)d_in[2];
    const float* W2  = (const float*)d_in[3];
    const float* b2  = (const float*)d_in[4];
    const float* W3  = (const float*)d_in[5];
    const int*   y   = (const int*)d_in[6];
    const void*  opt = (const void*)d_in[7];
    float* out = (float*)d_out;

    prep_kernel<<<320, 256>>>(emb, opt, b1, b2, out, out_size);
    gemm_kernel<0><<<dim3(HID/NTILE, KSPLIT), GTHR>>>(W1);
    gemm_kernel<1><<<dim3(HID/NTILE, KSPLIT), GTHR>>>(W2);
    gemv_loss_kernel<<<BSZ, 256>>>(W3, y, out, out_size);
}